// round 13
// baseline (speedup 1.0000x reference)
#include <cuda_runtime.h>
#include <cstdint>

// Tucker via time-bucketing, round 13: three kernels.
//   scatter : slot-scatter by k (int4 slots, CAP=96, overflow fallback)
//   build_w : W_k[p,q] = sum_r C[p,q,r] t_k[r] -> g_W (L2-resident, 20MB)
//   sample  : lane = sample. Per 32-sample pass one warp streams W rows as
//             UNIFORM LDG.128 (broadcast) and does all math in f32x2.
//             No SMEM, no shuffles -> 24 warps/SM.

#define NTIME       5000
#define NUM_CTAS    148
#define CAP         96

// ---- device scratch (zero-init at load) ----
__device__ int4  g_slot[NTIME * CAP];     // (idx, iu, ij, 0)
__device__ float g_W[NTIME * 1024];       // [b][p][q]
__device__ int   g_counts[NTIME];
__device__ int   g_ovf[4096];
__device__ int   g_ovf_cnt;
__device__ int   g_ticket_w;
__device__ int   g_ticket_s;

// ---- packed f32x2 helpers ----
#define PACK2(d, lo, hi) asm("mov.b64 %0, {%1, %2};" : "=l"(d) : "f"(lo), "f"(hi))
#define UNPACK2(lo, hi, s) asm("mov.b64 {%0, %1}, %2;" : "=f"(lo), "=f"(hi) : "l"(s))
#define FMA2(acc, a, b) asm("fma.rn.f32x2 %0, %1, %2, %0;" : "+l"(acc) : "l"(a), "l"(b))

// ============================ scatter ============================
__global__ void scatter_kernel(const int* __restrict__ k_in,
                               const int* __restrict__ i_in,
                               const int* __restrict__ j_in, int n) {
    int x = blockIdx.x * blockDim.x + threadIdx.x;
    if (x == 0) { g_ticket_w = 0; g_ticket_s = 0; }
    if (x < n) {
        int k  = k_in[x];
        int iu = i_in[x];
        int ij = j_in[x];
        int pos = atomicAdd(&g_counts[k], 1);
        if (pos < CAP) {
            g_slot[k * CAP + pos] = make_int4(x, iu, ij, 0);
        } else {
            int o = atomicAdd(&g_ovf_cnt, 1);
            if (o < 4096) g_ovf[o] = x;
        }
    }
}

// ============================ build_w ============================
// SMEM: C at Cs[(q*32 + p)*36 + r] (stride-36: conflict-free LDS.128, lane=p)
#define BW_THREADS 256
#define BW_G       4
#define BW_TASKS   (NTIME / BW_G)
#define ROW_STRIDE 36
#define BW_SMEM    (1024 * ROW_STRIDE * 4)

__global__ void __launch_bounds__(BW_THREADS, 1)
build_w_kernel(const float* __restrict__ T, const float* __restrict__ C)
{
    extern __shared__ float sm[];
    const int tid  = threadIdx.x;
    const int lane = tid & 31;   // = p

    for (int idx = tid; idx < 32768; idx += BW_THREADS) {
        int p = idx >> 10, q = (idx >> 5) & 31, r = idx & 31;
        sm[(q * 32 + p) * ROW_STRIDE + r] = C[idx];
    }
    __syncthreads();

    while (true) {
        int task;
        if (lane == 0) task = atomicAdd(&g_ticket_w, 1);
        task = __shfl_sync(0xffffffffu, task, 0);
        if (task >= BW_TASKS) break;

        const int b0 = task * BW_G;
        float tl[BW_G];
        #pragma unroll
        for (int g = 0; g < BW_G; g++) tl[g] = T[(size_t)(b0 + g) * 32 + lane];

        float w[BW_G][32];
        #pragma unroll
        for (int g = 0; g < BW_G; g++)
            #pragma unroll
            for (int q = 0; q < 32; q++) w[g][q] = 0.f;

        #pragma unroll 2
        for (int r4 = 0; r4 < 8; r4++) {
            float ta[BW_G], tb[BW_G], tc[BW_G], td[BW_G];
            #pragma unroll
            for (int g = 0; g < BW_G; g++) {
                ta[g] = __shfl_sync(0xffffffffu, tl[g], 4*r4 + 0);
                tb[g] = __shfl_sync(0xffffffffu, tl[g], 4*r4 + 1);
                tc[g] = __shfl_sync(0xffffffffu, tl[g], 4*r4 + 2);
                td[g] = __shfl_sync(0xffffffffu, tl[g], 4*r4 + 3);
            }
            #pragma unroll
            for (int q = 0; q < 32; q++) {
                float4 c4 = *(const float4*)&sm[(q * 32 + lane) * ROW_STRIDE + 4*r4];
                #pragma unroll
                for (int g = 0; g < BW_G; g++) {
                    w[g][q] = fmaf(c4.x, ta[g], w[g][q]);
                    w[g][q] = fmaf(c4.y, tb[g], w[g][q]);
                    w[g][q] = fmaf(c4.z, tc[g], w[g][q]);
                    w[g][q] = fmaf(c4.w, td[g], w[g][q]);
                }
            }
        }

        // store: g_W[b][p][q], lane = p owns its 128B row
        #pragma unroll
        for (int g = 0; g < BW_G; g++) {
            float* wb = g_W + (size_t)(b0 + g) * 1024 + lane * 32;
            #pragma unroll
            for (int q4 = 0; q4 < 8; q4++)
                *(float4*)&wb[4*q4] = make_float4(w[g][4*q4],   w[g][4*q4+1],
                                                  w[g][4*q4+2], w[g][4*q4+3]);
        }
    }
}

// ============================ sample ============================
#define SP_THREADS 768

__global__ void __launch_bounds__(SP_THREADS, 1)
sample_kernel(const int* __restrict__ i_in, const int* __restrict__ j_in,
              const int* __restrict__ k_in,
              const float* __restrict__ U, const float* __restrict__ V,
              const float* __restrict__ T, const float* __restrict__ C,
              float* __restrict__ out)
{
    const int tid  = threadIdx.x;
    const int wid  = tid >> 5;
    const int lane = tid & 31;   // = sample within pass

    // overflow slow path (expected 0 iterations) — global C
    if (blockIdx.x == 0 && wid == 0 && g_ovf_cnt > 0) {
        int no = min(g_ovf_cnt, 4096);
        for (int o = 0; o < no; o++) {
            int idx = g_ovf[o];
            int iu = i_in[idx], ij = j_in[idx], ik = k_in[idx];
            float up = U[(size_t)iu * 32 + lane];     // lane = p here
            float sp = 0.f;
            for (int q = 0; q < 32; q++) {
                float vq = V[(size_t)ij * 32 + q];
                float acc = 0.f;
                #pragma unroll
                for (int r4 = 0; r4 < 8; r4++) {
                    float4 c4 = *(const float4*)&C[((size_t)(lane * 32 + q)) * 32 + r4 * 4];
                    float4 t4 = *(const float4*)&T[(size_t)ik * 32 + r4 * 4];
                    acc += c4.x * t4.x + c4.y * t4.y + c4.z * t4.z + c4.w * t4.w;
                }
                sp = fmaf(vq, acc, sp);
            }
            float val = up * sp;
            #pragma unroll
            for (int off = 16; off > 0; off >>= 1)
                val += __shfl_xor_sync(0xffffffffu, val, off);
            if (lane == 0) out[idx] = val;
        }
        if (lane == 0) g_ovf_cnt = 0;
    }

    while (true) {
        int b;
        if (lane == 0) b = atomicAdd(&g_ticket_s, 1);
        b = __shfl_sync(0xffffffffu, b, 0);
        if (b >= NTIME) break;

        int cnt;
        if (lane == 0) { cnt = g_counts[b]; g_counts[b] = 0; }   // reset for replay
        cnt = __shfl_sync(0xffffffffu, cnt, 0);
        if (cnt == 0) continue;
        cnt = min(cnt, CAP);

        const float* __restrict__ Wb = g_W + (size_t)b * 1024;

        for (int base = 0; base < cnt; base += 32) {
            const int rem = cnt - base;
            int4 s4 = g_slot[b * CAP + base + min(lane, rem - 1)];
            const float* __restrict__ Urow = U + (size_t)s4.y * 32;
            const float* __restrict__ Vrow = V + (size_t)s4.z * 32;

            // a[q] (packed q-pairs) = sum_p u_p * W[p][q]
            unsigned long long a2[16];
            #pragma unroll
            for (int x = 0; x < 16; x++) a2[x] = 0ULL;

            #pragma unroll 2
            for (int p4 = 0; p4 < 8; p4++) {
                float4 u4 = *(const float4*)&Urow[4 * p4];   // per-lane gather
                #pragma unroll
                for (int pp = 0; pp < 4; pp++) {
                    float up = (pp == 0) ? u4.x : (pp == 1) ? u4.y
                             : (pp == 2) ? u4.z : u4.w;
                    unsigned long long upk;
                    PACK2(upk, up, up);
                    const ulonglong2* __restrict__ wr =
                        (const ulonglong2*)(Wb + (4 * p4 + pp) * 32);
                    #pragma unroll
                    for (int x = 0; x < 8; x++) {
                        ulonglong2 c = wr[x];                // uniform: 1 line
                        FMA2(a2[2 * x],     upk, c.x);
                        FMA2(a2[2 * x + 1], upk, c.y);
                    }
                }
            }

            // y = sum_q a_q * v_q
            unsigned long long acc = 0ULL;
            #pragma unroll
            for (int q4 = 0; q4 < 8; q4++) {
                float4 v4 = *(const float4*)&Vrow[4 * q4];
                unsigned long long v01, v23;
                PACK2(v01, v4.x, v4.y);
                PACK2(v23, v4.z, v4.w);
                FMA2(acc, a2[2 * q4],     v01);
                FMA2(acc, a2[2 * q4 + 1], v23);
            }
            float ylo, yhi;
            UNPACK2(ylo, yhi, acc);
            if (lane < rem) out[s4.x] = ylo + yhi;
        }
    }
}

// ============================ launch ============================
extern "C" void kernel_launch(void* const* d_in, const int* in_sizes, int n_in,
                              void* d_out, int out_size)
{
    const int*   i_in = (const int*)d_in[0];
    const int*   j_in = (const int*)d_in[1];
    const int*   k_in = (const int*)d_in[2];
    const float* U    = (const float*)d_in[3];
    const float* V    = (const float*)d_in[4];
    const float* T    = (const float*)d_in[5];
    const float* C    = (const float*)d_in[6];
    float*       out  = (float*)d_out;

    const int n = in_sizes[0];

    static bool configured = false;
    if (!configured) {
        cudaFuncSetAttribute(build_w_kernel,
                             cudaFuncAttributeMaxDynamicSharedMemorySize, BW_SMEM);
        configured = true;
    }

    scatter_kernel<<<(n + 255) / 256, 256>>>(k_in, i_in, j_in, n);
    build_w_kernel<<<NUM_CTAS, BW_THREADS, BW_SMEM>>>(T, C);
    sample_kernel<<<NUM_CTAS, SP_THREADS>>>(i_in, j_in, k_in, U, V, T, C, out);
}

// round 14
// speedup vs baseline: 1.4478x; 1.4478x over previous
#include <cuda_runtime.h>
#include <cstdint>

// Tucker via time-bucketing, round 14:
//   y_n = u_n^T W_{k_n} v_n,   W_k[p,q] = sum_r C[p,q,r] t_k[r]
// main: warp-task = ONE bucket. W built lane=p in regs, staged to per-warp
// SMEM (stride-36 rows), sample phase lane=sample with UNIFORM LDS.128
// broadcasts of W rows + f32x2 math  (~26 issues/sample).

#define NTIME       5000
#define NUM_CTAS    148
#define CTA_THREADS 512
#define WARPS       (CTA_THREADS / 32)
#define CAP         96

// ---- device scratch (zero-init at load) ----
__device__ int4 g_slot[NTIME * CAP];     // (idx, iu, ij, 0)
__device__ int  g_counts[NTIME];
__device__ int  g_ovf[4096];
__device__ int  g_ovf_cnt;
__device__ int  g_ticket;

// ---- packed f32x2 helpers ----
#define PACK2(d, lo, hi) asm("mov.b64 %0, {%1, %2};" : "=l"(d) : "f"(lo), "f"(hi))
#define UNPACK2(lo, hi, s) asm("mov.b64 {%0, %1}, %2;" : "=f"(lo), "=f"(hi) : "l"(s))
#define FMA2(acc, a, b) asm("fma.rn.f32x2 %0, %1, %2, %0;" : "+l"(acc) : "l"(a), "l"(b))
#define LDSV2U64(d0, d1, addr) \
    asm volatile("ld.shared.v2.u64 {%0, %1}, [%2];" : "=l"(d0), "=l"(d1) : "r"(addr))

__device__ __forceinline__ uint32_t smem_u32(const void* p) {
    uint32_t a;
    asm("{ .reg .u64 t; cvta.to.shared.u64 t, %1; cvt.u32.u64 %0, t; }" : "=r"(a) : "l"(p));
    return a;
}

// ============================ scatter ============================
__global__ void scatter_kernel(const int* __restrict__ k_in,
                               const int* __restrict__ i_in,
                               const int* __restrict__ j_in, int n) {
    int x = blockIdx.x * blockDim.x + threadIdx.x;
    if (x == 0) g_ticket = 0;            // consumed by the later kernel
    if (x < n) {
        int k  = k_in[x];
        int iu = i_in[x];
        int ij = j_in[x];
        int pos = atomicAdd(&g_counts[k], 1);
        if (pos < CAP) {
            g_slot[k * CAP + pos] = make_int4(x, iu, ij, 0);
        } else {
            int o = atomicAdd(&g_ovf_cnt, 1);
            if (o < 4096) g_ovf[o] = x;
        }
    }
}

// ============================ main ============================
// SMEM (floats):
//   [0, 36864)        C: Cs[(q*32 + p)*36 + r]  (stride-36, conflict-free LDS.128)
//   per warp w:       36864 + wid*1152 : W staging, Wst[p*36 + q] (16B aligned)
#define ROW_STRIDE  36
#define PW_FLOATS   (32 * ROW_STRIDE)
#define SMEM_FLOATS (1024 * ROW_STRIDE + WARPS * PW_FLOATS)
#define SMEM_BYTES  (SMEM_FLOATS * 4)

__global__ void __launch_bounds__(CTA_THREADS, 1)
tucker_main(const int* __restrict__ i_in, const int* __restrict__ j_in,
            const int* __restrict__ k_in,
            const float* __restrict__ U, const float* __restrict__ V,
            const float* __restrict__ T, const float* __restrict__ C,
            float* __restrict__ out)
{
    extern __shared__ float sm[];
    const uint32_t smb = smem_u32(sm);
    const int tid  = threadIdx.x;
    const int wid  = tid >> 5;
    const int lane = tid & 31;

    // stage C: C[p][q][r] -> Cs[(q*32+p)*36 + r]
    for (int idx = tid; idx < 32768; idx += CTA_THREADS) {
        int p = idx >> 10, q = (idx >> 5) & 31, r = idx & 31;
        sm[(q * 32 + p) * ROW_STRIDE + r] = C[idx];
    }
    __syncthreads();

    // overflow slow path (expected 0 iterations) — reads C from global
    if (blockIdx.x == 0 && wid == 0 && g_ovf_cnt > 0) {
        int no = min(g_ovf_cnt, 4096);
        for (int o = 0; o < no; o++) {
            int idx = g_ovf[o];
            int iu = i_in[idx], ij = j_in[idx], ik = k_in[idx];
            float up = U[(size_t)iu * 32 + lane];     // lane = p
            float sp = 0.f;
            for (int q = 0; q < 32; q++) {
                float vq = V[(size_t)ij * 32 + q];
                float acc = 0.f;
                #pragma unroll
                for (int r4 = 0; r4 < 8; r4++) {
                    float4 c4 = *(const float4*)&C[((size_t)(lane * 32 + q)) * 32 + r4 * 4];
                    float4 t4 = *(const float4*)&T[(size_t)ik * 32 + r4 * 4];
                    acc += c4.x * t4.x + c4.y * t4.y + c4.z * t4.z + c4.w * t4.w;
                }
                sp = fmaf(vq, acc, sp);
            }
            float val = up * sp;
            #pragma unroll
            for (int off = 16; off > 0; off >>= 1)
                val += __shfl_xor_sync(0xffffffffu, val, off);
            if (lane == 0) out[idx] = val;
        }
        if (lane == 0) g_ovf_cnt = 0;    // reset for next replay
    }

    float*         Wst   = sm + 1024 * ROW_STRIDE + wid * PW_FLOATS;
    const uint32_t Wst_a = smb + (1024 * ROW_STRIDE + wid * PW_FLOATS) * 4u;

    while (true) {
        int b;
        if (lane == 0) b = atomicAdd(&g_ticket, 1);
        b = __shfl_sync(0xffffffffu, b, 0);
        if (b >= NTIME) break;

        int cnt;
        if (lane == 0) { cnt = g_counts[b]; g_counts[b] = 0; }   // reset for replay
        cnt = __shfl_sync(0xffffffffu, cnt, 0);
        if (cnt == 0) continue;
        cnt = min(cnt, CAP);

        // ---- W build (lane = p): w[q] = sum_r C[p][q][r] * t[r] ----
        {
            const float tl = T[(size_t)b * 32 + lane];   // lane = r
            float w[32];
            #pragma unroll
            for (int q = 0; q < 32; q++) w[q] = 0.f;

            #pragma unroll 2
            for (int r4 = 0; r4 < 8; r4++) {
                float ta = __shfl_sync(0xffffffffu, tl, 4*r4 + 0);
                float tb = __shfl_sync(0xffffffffu, tl, 4*r4 + 1);
                float tc = __shfl_sync(0xffffffffu, tl, 4*r4 + 2);
                float td = __shfl_sync(0xffffffffu, tl, 4*r4 + 3);
                #pragma unroll
                for (int q = 0; q < 32; q++) {
                    float4 c4 = *(const float4*)&sm[(q * 32 + lane) * ROW_STRIDE + 4*r4];
                    w[q] = fmaf(c4.x, ta, w[q]);
                    w[q] = fmaf(c4.y, tb, w[q]);
                    w[q] = fmaf(c4.z, tc, w[q]);
                    w[q] = fmaf(c4.w, td, w[q]);
                }
            }

            // stage W: lane p owns row Wst[p*36 .. +32)
            float* wrow = Wst + lane * ROW_STRIDE;
            #pragma unroll
            for (int q4 = 0; q4 < 8; q4++)
                *(float4*)&wrow[4*q4] = make_float4(w[4*q4],   w[4*q4+1],
                                                    w[4*q4+2], w[4*q4+3]);
        }
        __syncwarp();

        // ---- sample phase (lane = sample) ----
        for (int base = 0; base < cnt; base += 32) {
            const int rem = cnt - base;
            int4 s4 = g_slot[b * CAP + base + min(lane, rem - 1)];
            const float* __restrict__ Urow = U + (size_t)s4.y * 32;
            const float* __restrict__ Vrow = V + (size_t)s4.z * 32;

            // a[q] (packed q-pairs) = sum_p u_p * W[p][q]
            unsigned long long a2[16];
            #pragma unroll
            for (int x = 0; x < 16; x++) a2[x] = 0ULL;

            #pragma unroll 4
            for (int p4 = 0; p4 < 8; p4++) {
                float4 u4 = *(const float4*)&Urow[4 * p4];   // per-lane gather
                #pragma unroll
                for (int pp = 0; pp < 4; pp++) {
                    float up = (pp == 0) ? u4.x : (pp == 1) ? u4.y
                             : (pp == 2) ? u4.z : u4.w;
                    unsigned long long upk;
                    PACK2(upk, up, up);
                    const uint32_t row = Wst_a + (uint32_t)(4 * p4 + pp) * (ROW_STRIDE * 4);
                    #pragma unroll
                    for (int x = 0; x < 8; x++) {
                        unsigned long long c0, c1;
                        LDSV2U64(c0, c1, row + x * 16u);     // uniform broadcast
                        FMA2(a2[2 * x],     upk, c0);
                        FMA2(a2[2 * x + 1], upk, c1);
                    }
                }
            }

            // y = sum_q a_q * v_q
            unsigned long long acc = 0ULL;
            #pragma unroll
            for (int q4 = 0; q4 < 8; q4++) {
                float4 v4 = *(const float4*)&Vrow[4 * q4];
                unsigned long long v01, v23;
                PACK2(v01, v4.x, v4.y);
                PACK2(v23, v4.z, v4.w);
                FMA2(acc, a2[2 * q4],     v01);
                FMA2(acc, a2[2 * q4 + 1], v23);
            }
            float ylo, yhi;
            UNPACK2(ylo, yhi, acc);
            if (lane < rem) out[s4.x] = ylo + yhi;
        }
        __syncwarp();   // Wst reused next task
    }
}

extern "C" void kernel_launch(void* const* d_in, const int* in_sizes, int n_in,
                              void* d_out, int out_size)
{
    const int*   i_in = (const int*)d_in[0];
    const int*   j_in = (const int*)d_in[1];
    const int*   k_in = (const int*)d_in[2];
    const float* U    = (const float*)d_in[3];
    const float* V    = (const float*)d_in[4];
    const float* T    = (const float*)d_in[5];
    const float* C    = (const float*)d_in[6];
    float*       out  = (float*)d_out;

    const int n = in_sizes[0];

    static bool configured = false;
    if (!configured) {
        cudaFuncSetAttribute(tucker_main,
                             cudaFuncAttributeMaxDynamicSharedMemorySize,
                             SMEM_BYTES);
        configured = true;
    }

    scatter_kernel<<<(n + 255) / 256, 256>>>(k_in, i_in, j_in, n);
    tucker_main<<<NUM_CTAS, CTA_THREADS, SMEM_BYTES>>>(i_in, j_in, k_in,
                                                       U, V, T, C, out);
}